// round 13
// baseline (speedup 1.0000x reference)
#include <cuda_runtime.h>
#include <cuda_fp16.h>
#include <cstdint>
#include <math.h>

#define NE   8
#define HD   2048
#define ID   1024
#define NT   8192
#define TOPK 2
#define MAXP (NT * TOPK)

// smem geometry (fp16 elems)
#define SAW    40                    // A row stride: 32 data + 8 pad (80 B)
#define SBW    136                   // B row stride: 128 data + 8 pad (272 B)
#define ABYTES (128 * SAW * 2)       // 10240
#define BBYTES (32 * SBW * 2)        // 8704

// both GEMMs: A single-term fp16
#define BOFF   ABYTES                // 10240
#define STAGE  (BOFF + BBYTES)       // 18944
#define SMEM_SZ (3 * STAGE)          // 56832  -> 2 CTA/SM (regs are the cap)

// ---- device globals ----
__device__ int    g_cnt[NE];
__device__ int    g_pair[NE * MAXP];
__device__ __half g_x_h[(size_t)NT * HD];
__device__ __half g_gw[(size_t)NE * HD * ID];
__device__ __half g_uw[(size_t)NE * HD * ID];
__device__ __half g_dw[(size_t)NE * ID * HD];
__device__ __half g_act[(size_t)MAXP * ID];
__device__ float  g_ds[(size_t)MAXP * HD];

// ============================ asm helpers ============================
__device__ __forceinline__ uint32_t smem_to_u32(const void* p) {
    uint32_t a;
    asm("{ .reg .u64 t; cvta.to.shared.u64 t, %1; cvt.u32.u64 %0, t; }" : "=r"(a) : "l"(p));
    return a;
}
__device__ __forceinline__ void ldm_x4(uint32_t* r, uint32_t a) {
    asm volatile("ldmatrix.sync.aligned.m8n8.x4.shared.b16 {%0,%1,%2,%3}, [%4];"
                 : "=r"(r[0]), "=r"(r[1]), "=r"(r[2]), "=r"(r[3]) : "r"(a));
}
__device__ __forceinline__ void ldm_x4_t(uint32_t* r, uint32_t a) {
    asm volatile("ldmatrix.sync.aligned.m8n8.x4.trans.shared.b16 {%0,%1,%2,%3}, [%4];"
                 : "=r"(r[0]), "=r"(r[1]), "=r"(r[2]), "=r"(r[3]) : "r"(a));
}
__device__ __forceinline__ void mma16816(float* c, const uint32_t* a, uint32_t b0, uint32_t b1) {
    asm volatile("mma.sync.aligned.m16n8k16.row.col.f32.f16.f16.f32 "
                 "{%0,%1,%2,%3}, {%4,%5,%6,%7}, {%8,%9}, {%0,%1,%2,%3};"
                 : "+f"(c[0]), "+f"(c[1]), "+f"(c[2]), "+f"(c[3])
                 : "r"(a[0]), "r"(a[1]), "r"(a[2]), "r"(a[3]), "r"(b0), "r"(b1));
}
#define CP16(dst, src) \
    asm volatile("cp.async.cg.shared.global [%0], [%1], 16;" :: "r"(dst), "l"(src) : "memory")
#define CP16Z(dst, src, n) \
    asm volatile("cp.async.cg.shared.global [%0], [%1], 16, %2;" :: "r"(dst), "l"(src), "r"(n) : "memory")
#define CP_COMMIT() asm volatile("cp.async.commit_group;" ::: "memory")
#define CP_WAIT1()  asm volatile("cp.async.wait_group 1;" ::: "memory")
#define CP_WAIT0()  asm volatile("cp.async.wait_group 0;" ::: "memory")

__device__ __forceinline__ float gelu_tanh(float gv) {
    float t  = gv + 0.044715f * gv * gv * gv;
    float z  = 1.5957691216057308f * t;
    float th = 1.0f - 2.0f / (__expf(z) + 1.0f);
    return 0.5f * gv * (1.0f + th);
}
__device__ __forceinline__ uint32_t pkh(__half a, __half b) {
    __half2 t = __halves2half2(a, b);
    return *reinterpret_cast<uint32_t*>(&t);
}

// ============================ prep kernels ============================
__global__ void k_zero_counts() { if (threadIdx.x < NE) g_cnt[threadIdx.x] = 0; }

__global__ void k_route(const int* __restrict__ sel) {
    int p = blockIdx.x * blockDim.x + threadIdx.x;
    if (p < MAXP) {
        int e = sel[p];
        int pos = atomicAdd(&g_cnt[e], 1);
        g_pair[e * MAXP + pos] = p;
    }
}

// fp32 -> fp16, 2 float4 per thread for ILP
__global__ void k_half8(const float* __restrict__ src, __half* __restrict__ dst, int n4) {
    int i = (blockIdx.x * blockDim.x + threadIdx.x) * 2;
    if (i + 1 >= n4) {
        if (i < n4) {
            float4 v = ((const float4*)src)[i];
            __half2 a = __floats2half2_rn(v.x, v.y);
            __half2 b = __floats2half2_rn(v.z, v.w);
            ((uint2*)dst)[i] = make_uint2(*(uint32_t*)&a, *(uint32_t*)&b);
        }
        return;
    }
    float4 v0 = ((const float4*)src)[i];
    float4 v1 = ((const float4*)src)[i + 1];
    __half2 a0 = __floats2half2_rn(v0.x, v0.y), b0 = __floats2half2_rn(v0.z, v0.w);
    __half2 a1 = __floats2half2_rn(v1.x, v1.y), b1 = __floats2half2_rn(v1.z, v1.w);
    uint4 o = make_uint4(*(uint32_t*)&a0, *(uint32_t*)&b0, *(uint32_t*)&a1, *(uint32_t*)&b1);
    ((uint4*)dst)[i >> 1] = o;
}

// ============================ issue helpers ============================
// A 128x32 single fp16 (1 cp/thread), B 32x128 (1 cp/thread)
__device__ __forceinline__ void gu_issue(int ck, int st, uint32_t sbd, const int* sPair,
                                         const __half* gw, const __half* uw,
                                         int cb, int tid)
{
    uint32_t sbase = sbd + st * STAGE;
    {
        int r = tid >> 2, c = tid & 3;
        int pr = sPair[r];
        const __half* src = g_x_h
                          + ((size_t)((pr >= 0) ? (pr >> 1) : 0) * HD + ck * 32 + c * 8);
        uint32_t dst = sbase + (uint32_t)(r * SAW + c * 8) * 2;
        CP16Z(dst, src, (pr >= 0) ? 16u : 0u);
    }
    {
        int r = tid >> 4, c = tid & 15;           // c: 0..7 gate, 8..15 up
        const __half* w = (c < 8) ? gw : uw;
        const __half* src = w + (size_t)(ck * 32 + r) * ID + cb * 64 + (c & 7) * 8;
        uint32_t dst = sbase + BOFF + (uint32_t)(r * SBW + c * 8) * 2;
        CP16(dst, src);
    }
    CP_COMMIT();
}

__device__ __forceinline__ void dn_issue(int ck, int st, uint32_t sbd, const int* sPair,
                                         const __half* dw, int cb, int tid)
{
    uint32_t sbase = sbd + st * STAGE;
    {
        int r = tid >> 2, c = tid & 3;
        int pr = sPair[r];
        const __half* src = g_act
                          + ((size_t)((pr >= 0) ? pr : 0) * ID + ck * 32 + c * 8);
        uint32_t dst = sbase + (uint32_t)(r * SAW + c * 8) * 2;
        CP16Z(dst, src, (pr >= 0) ? 16u : 0u);
    }
    {
        int r = tid >> 4, c = tid & 15;
        const __half* src = dw + (size_t)(ck * 32 + r) * HD + cb * 128 + c * 8;
        uint32_t dst = sbase + BOFF + (uint32_t)(r * SBW + c * 8) * 2;
        CP16(dst, src);
    }
    CP_COMMIT();
}

// ============================ gate+up ============================
// CTA: 128 pairs x (64 gate + 64 up cols), K=HD, 32-chunks, 3-stage, 2 CTA/SM.
__global__ __launch_bounds__(512, 2)
void k_gateup(const float* __restrict__ rw)
{
    const int e = blockIdx.z;
    const int cnt = g_cnt[e];
    const int row0 = blockIdx.y * 128;
    if (row0 >= cnt) return;
    const int cb = blockIdx.x;

    extern __shared__ char smem[];
    __shared__ int sPair[128];
    const uint32_t sbd = smem_to_u32(smem);
    const int tid = threadIdx.x, wid = tid >> 5, lane = tid & 31;
    const int wm = wid >> 2, wn = wid & 3;

    if (tid < 128) {
        int pos = row0 + tid;
        sPair[tid] = (pos < cnt) ? g_pair[e * MAXP + pos] : -1;
    }
    __syncthreads();

    const __half* gw = g_gw + (size_t)e * HD * ID;
    const __half* uw = g_uw + (size_t)e * HD * ID;

    float acc[2][2][2][4];
    #pragma unroll
    for (int i = 0; i < 2; ++i)
        #pragma unroll
        for (int j = 0; j < 2; ++j)
            #pragma unroll
            for (int s = 0; s < 2; ++s)
                #pragma unroll
                for (int q = 0; q < 4; ++q) acc[i][j][s][q] = 0.f;

    gu_issue(0, 0, sbd, sPair, gw, uw, cb, tid);
    gu_issue(1, 1, sbd, sPair, gw, uw, cb, tid);

    const int NCK = HD / 32;
    for (int ck = 0; ck < NCK; ++ck) {
        if (ck < NCK - 1) CP_WAIT1(); else CP_WAIT0();
        __syncthreads();

        const int st = ck % 3;
        uint32_t uA = sbd + st * STAGE;
        uint32_t uB = uA + BOFF;
        #pragma unroll
        for (int ks = 0; ks < 2; ++ks) {
            uint32_t b[8];
            uint32_t brow = (uint32_t)(ks * 16 + (lane & 15));
            uint32_t co   = (uint32_t)((lane >> 4) << 3);
            ldm_x4_t(b,     uB + (brow * SBW + wn * 16 + co) * 2);
            ldm_x4_t(b + 4, uB + (brow * SBW + 64 + wn * 16 + co) * 2);
            #pragma unroll
            for (int mt = 0; mt < 2; ++mt) {
                uint32_t a[4];
                uint32_t off = (uint32_t)((wm * 32 + mt * 16 + (lane & 15)) * SAW
                                          + ks * 16 + co) * 2;
                ldm_x4(a, uA + off);
                mma16816(acc[mt][0][0], a, b[0], b[1]);
                mma16816(acc[mt][0][1], a, b[2], b[3]);
                mma16816(acc[mt][1][0], a, b[4], b[5]);
                mma16816(acc[mt][1][1], a, b[6], b[7]);
            }
        }
        if (ck + 2 < NCK) gu_issue(ck + 2, (ck + 2) % 3, sbd, sPair, gw, uw, cb, tid);
    }

    // epilogue: act = rw * gelu(gate) * up -> single fp16 scratch
    #pragma unroll
    for (int mt = 0; mt < 2; ++mt)
        #pragma unroll
        for (int s = 0; s < 2; ++s) {
            int c = cb * 64 + wn * 16 + s * 8 + (lane & 3) * 2;
            #pragma unroll
            for (int half = 0; half < 2; ++half) {
                int r = wm * 32 + mt * 16 + (lane >> 2) + half * 8;
                int pr = sPair[r];
                if (pr < 0) continue;
                float wgt = rw[pr];
                float g0 = acc[mt][0][s][half * 2], g1 = acc[mt][0][s][half * 2 + 1];
                float u0 = acc[mt][1][s][half * 2], u1 = acc[mt][1][s][half * 2 + 1];
                float o0 = wgt * gelu_tanh(g0) * u0;
                float o1 = wgt * gelu_tanh(g1) * u1;
                *(uint32_t*)(g_act + (size_t)pr * ID + c) =
                    pkh(__float2half_rn(o0), __float2half_rn(o1));
            }
        }
}

// ============================ down ============================
// CTA: 128 pairs x 128 hidden cols, K=ID, 32-chunks, 3-stage, 2 CTA/SM.
__global__ __launch_bounds__(512, 2)
void k_down()
{
    const int e = blockIdx.z;
    const int cnt = g_cnt[e];
    const int row0 = blockIdx.y * 128;
    if (row0 >= cnt) return;
    const int cb = blockIdx.x;

    extern __shared__ char smem[];
    __shared__ int sPair[128];
    const uint32_t sbd = smem_to_u32(smem);
    const int tid = threadIdx.x, wid = tid >> 5, lane = tid & 31;
    const int wm = wid >> 2, wn = wid & 3;

    if (tid < 128) {
        int pos = row0 + tid;
        sPair[tid] = (pos < cnt) ? g_pair[e * MAXP + pos] : -1;
    }
    __syncthreads();

    const __half* dw = g_dw + (size_t)e * ID * HD;

    float acc[2][4][4];
    #pragma unroll
    for (int i = 0; i < 2; ++i)
        #pragma unroll
        for (int j = 0; j < 4; ++j)
            #pragma unroll
            for (int q = 0; q < 4; ++q) acc[i][j][q] = 0.f;

    dn_issue(0, 0, sbd, sPair, dw, cb, tid);
    dn_issue(1, 1, sbd, sPair, dw, cb, tid);

    const int NCK = ID / 32;
    for (int ck = 0; ck < NCK; ++ck) {
        if (ck < NCK - 1) CP_WAIT1(); else CP_WAIT0();
        __syncthreads();

        const int st = ck % 3;
        uint32_t uA = sbd + st * STAGE;
        uint32_t uB = uA + BOFF;
        #pragma unroll
        for (int ks = 0; ks < 2; ++ks) {
            uint32_t b[8];
            uint32_t brow = (uint32_t)(ks * 16 + (lane & 15));
            uint32_t co   = (uint32_t)((lane >> 4) << 3);
            ldm_x4_t(b,     uB + (brow * SBW + wn * 32 + co) * 2);
            ldm_x4_t(b + 4, uB + (brow * SBW + wn * 32 + 16 + co) * 2);
            #pragma unroll
            for (int mt = 0; mt < 2; ++mt) {
                uint32_t a[4];
                uint32_t off = (uint32_t)((wm * 32 + mt * 16 + (lane & 15)) * SAW
                                          + ks * 16 + co) * 2;
                ldm_x4(a, uA + off);
                mma16816(acc[mt][0], a, b[0], b[1]);
                mma16816(acc[mt][1], a, b[2], b[3]);
                mma16816(acc[mt][2], a, b[4], b[5]);
                mma16816(acc[mt][3], a, b[6], b[7]);
            }
        }
        if (ck + 2 < NCK) dn_issue(ck + 2, (ck + 2) % 3, sbd, sPair, dw, cb, tid);
    }

    // epilogue: per-pair fp32 scratch
    #pragma unroll
    for (int mt = 0; mt < 2; ++mt)
        #pragma unroll
        for (int j = 0; j < 4; ++j) {
            int c = cb * 128 + wn * 32 + j * 8 + (lane & 3) * 2;
            #pragma unroll
            for (int half = 0; half < 2; ++half) {
                int r = wm * 32 + mt * 16 + (lane >> 2) + half * 8;
                int pr = sPair[r];
                if (pr < 0) continue;
                float2 v = make_float2(acc[mt][j][half * 2], acc[mt][j][half * 2 + 1]);
                *(float2*)(g_ds + (size_t)pr * HD + c) = v;
            }
        }
}

// ============================ combine ============================
__global__ void k_combine(float* __restrict__ out) {
    int idx = blockIdx.x * blockDim.x + threadIdx.x;
    int t  = idx >> 9;
    int c4 = idx & 511;
    const float4* s4 = (const float4*)g_ds;
    float4 a = s4[(size_t)(2 * t) * 512 + c4];
    float4 b = s4[(size_t)(2 * t + 1) * 512 + c4];
    ((float4*)out)[idx] = make_float4(a.x + b.x, a.y + b.y, a.z + b.z, a.w + b.w);
}

// ============================ host ============================
extern "C" void kernel_launch(void* const* d_in, const int* in_sizes, int n_in,
                              void* d_out, int out_size)
{
    const float* x      = (const float*)d_in[0];
    const int*   sel    = (const int*)  d_in[1];
    const float* rw     = (const float*)d_in[2];
    const float* gate_w = (const float*)d_in[3];
    const float* up_w   = (const float*)d_in[4];
    const float* down_w = (const float*)d_in[5];
    float* out = (float*)d_out;

    cudaFuncSetAttribute(k_gateup, cudaFuncAttributeMaxDynamicSharedMemorySize, SMEM_SZ);
    cudaFuncSetAttribute(k_down,   cudaFuncAttributeMaxDynamicSharedMemorySize, SMEM_SZ);

    k_zero_counts<<<1, 32>>>();
    k_route<<<MAXP / 256, 256>>>(sel);

    {
        __half *xh, *gw, *uw, *dww;
        cudaGetSymbolAddress((void**)&xh,  g_x_h);
        cudaGetSymbolAddress((void**)&gw,  g_gw);
        cudaGetSymbolAddress((void**)&uw,  g_uw);
        cudaGetSymbolAddress((void**)&dww, g_dw);
        int nx4 = NT * HD / 4;
        int nw4 = NE * HD * ID / 4;
        k_half8<<<(nx4 / 2 + 255) / 256, 256>>>(x, xh, nx4);
        k_half8<<<(nw4 / 2 + 255) / 256, 256>>>(gate_w, gw, nw4);
        k_half8<<<(nw4 / 2 + 255) / 256, 256>>>(up_w,   uw, nw4);
        k_half8<<<(nw4 / 2 + 255) / 256, 256>>>(down_w, dww, nw4);
    }

    dim3 g1(ID / 64, MAXP / 128, NE);    // 16 x 128 x 8
    k_gateup<<<g1, 512, SMEM_SZ>>>(rw);

    dim3 g2(HD / 128, MAXP / 128, NE);   // 16 x 128 x 8
    k_down<<<g2, 512, SMEM_SZ>>>();

    k_combine<<<(NT * HD / 4) / 256, 256>>>(out);
}

// round 14
// speedup vs baseline: 1.6188x; 1.6188x over previous
#include <cuda_runtime.h>
#include <cuda_fp16.h>
#include <cstdint>
#include <math.h>

#define NE   8
#define HD   2048
#define ID   1024
#define NT   8192
#define TOPK 2
#define MAXP (NT * TOPK)

// smem geometry (fp16 elems)
#define SAW    40                    // A row stride: 32 data + 8 pad (80 B)
#define SBW    136                   // B row stride: 128 data + 8 pad (272 B)
#define ABYTES (128 * SAW * 2)       // 10240
#define BBYTES (32 * SBW * 2)        // 8704
#define BOFF   ABYTES                // 10240
#define STAGE  (BOFF + BBYTES)       // 18944
#define SMEM_SZ (3 * STAGE)          // 56832 -> 2 CTA/SM

// ---- device globals ----
__device__ int    g_cnt[NE];
__device__ int    g_pair[NE * MAXP];
__device__ __half g_x_h[(size_t)NT * HD];
__device__ __half g_gw[(size_t)NE * HD * ID];
__device__ __half g_uw[(size_t)NE * HD * ID];
__device__ __half g_dw[(size_t)NE * ID * HD];
__device__ __half g_act[(size_t)MAXP * ID];
__device__ float  g_ds[(size_t)MAXP * HD];

// ============================ asm helpers ============================
__device__ __forceinline__ uint32_t smem_to_u32(const void* p) {
    uint32_t a;
    asm("{ .reg .u64 t; cvta.to.shared.u64 t, %1; cvt.u32.u64 %0, t; }" : "=r"(a) : "l"(p));
    return a;
}
__device__ __forceinline__ void ldm_x4(uint32_t* r, uint32_t a) {
    asm volatile("ldmatrix.sync.aligned.m8n8.x4.shared.b16 {%0,%1,%2,%3}, [%4];"
                 : "=r"(r[0]), "=r"(r[1]), "=r"(r[2]), "=r"(r[3]) : "r"(a));
}
__device__ __forceinline__ void ldm_x4_t(uint32_t* r, uint32_t a) {
    asm volatile("ldmatrix.sync.aligned.m8n8.x4.trans.shared.b16 {%0,%1,%2,%3}, [%4];"
                 : "=r"(r[0]), "=r"(r[1]), "=r"(r[2]), "=r"(r[3]) : "r"(a));
}
__device__ __forceinline__ void mma16816(float* c, const uint32_t* a, uint32_t b0, uint32_t b1) {
    asm volatile("mma.sync.aligned.m16n8k16.row.col.f32.f16.f16.f32 "
                 "{%0,%1,%2,%3}, {%4,%5,%6,%7}, {%8,%9}, {%0,%1,%2,%3};"
                 : "+f"(c[0]), "+f"(c[1]), "+f"(c[2]), "+f"(c[3])
                 : "r"(a[0]), "r"(a[1]), "r"(a[2]), "r"(a[3]), "r"(b0), "r"(b1));
}
#define CP16(dst, src) \
    asm volatile("cp.async.cg.shared.global [%0], [%1], 16;" :: "r"(dst), "l"(src) : "memory")
#define CP16Z(dst, src, n) \
    asm volatile("cp.async.cg.shared.global [%0], [%1], 16, %2;" :: "r"(dst), "l"(src), "r"(n) : "memory")
#define CP_COMMIT() asm volatile("cp.async.commit_group;" ::: "memory")
#define CP_WAIT1()  asm volatile("cp.async.wait_group 1;" ::: "memory")
#define CP_WAIT0()  asm volatile("cp.async.wait_group 0;" ::: "memory")

__device__ __forceinline__ float gelu_tanh(float gv) {
    float t  = gv + 0.044715f * gv * gv * gv;
    float z  = 1.5957691216057308f * t;
    float th = 1.0f - 2.0f / (__expf(z) + 1.0f);
    return 0.5f * gv * (1.0f + th);
}
__device__ __forceinline__ uint32_t pkh(__half a, __half b) {
    __half2 t = __halves2half2(a, b);
    return *reinterpret_cast<uint32_t*>(&t);
}

// ============================ prep kernels ============================
__global__ void k_zero_counts() { if (threadIdx.x < NE) g_cnt[threadIdx.x] = 0; }

__global__ void k_route(const int* __restrict__ sel) {
    int p = blockIdx.x * blockDim.x + threadIdx.x;
    if (p < MAXP) {
        int e = sel[p];
        int pos = atomicAdd(&g_cnt[e], 1);
        g_pair[e * MAXP + pos] = p;
    }
}

__global__ void k_half8(const float* __restrict__ src, __half* __restrict__ dst, int n4) {
    int i = (blockIdx.x * blockDim.x + threadIdx.x) * 2;
    if (i + 1 >= n4) {
        if (i < n4) {
            float4 v = ((const float4*)src)[i];
            __half2 a = __floats2half2_rn(v.x, v.y);
            __half2 b = __floats2half2_rn(v.z, v.w);
            ((uint2*)dst)[i] = make_uint2(*(uint32_t*)&a, *(uint32_t*)&b);
        }
        return;
    }
    float4 v0 = ((const float4*)src)[i];
    float4 v1 = ((const float4*)src)[i + 1];
    __half2 a0 = __floats2half2_rn(v0.x, v0.y), b0 = __floats2half2_rn(v0.z, v0.w);
    __half2 a1 = __floats2half2_rn(v1.x, v1.y), b1 = __floats2half2_rn(v1.z, v1.w);
    ((uint4*)dst)[i >> 1] =
        make_uint4(*(uint32_t*)&a0, *(uint32_t*)&b0, *(uint32_t*)&a1, *(uint32_t*)&b1);
}

// ============================ issue helpers (256 threads) ============================
// A tile 128x32 fp16: 512 x16B -> 2 cp/thread. B tile 32x128: 512 x16B -> 2 cp/thread.
__device__ __forceinline__ void gu_issue(int ck, int st, uint32_t sbd, const int* sPair,
                                         const __half* gw, const __half* uw,
                                         int cb, int tid)
{
    uint32_t sbase = sbd + st * STAGE;
    #pragma unroll
    for (int it = 0; it < 2; ++it) {
        int s = tid + it * 256;
        int r = s >> 2, c = s & 3;
        int pr = sPair[r];
        const __half* src = g_x_h
                          + ((size_t)((pr >= 0) ? (pr >> 1) : 0) * HD + ck * 32 + c * 8);
        uint32_t dst = sbase + (uint32_t)(r * SAW + c * 8) * 2;
        CP16Z(dst, src, (pr >= 0) ? 16u : 0u);
    }
    #pragma unroll
    for (int it = 0; it < 2; ++it) {
        int s = tid + it * 256;
        int r = s >> 4, c = s & 15;               // c: 0..7 gate, 8..15 up
        const __half* w = (c < 8) ? gw : uw;
        const __half* src = w + (size_t)(ck * 32 + r) * ID + cb * 64 + (c & 7) * 8;
        uint32_t dst = sbase + BOFF + (uint32_t)(r * SBW + c * 8) * 2;
        CP16(dst, src);
    }
    CP_COMMIT();
}

__device__ __forceinline__ void dn_issue(int ck, int st, uint32_t sbd, const int* sPair,
                                         const __half* dw, int cb, int tid)
{
    uint32_t sbase = sbd + st * STAGE;
    #pragma unroll
    for (int it = 0; it < 2; ++it) {
        int s = tid + it * 256;
        int r = s >> 2, c = s & 3;
        int pr = sPair[r];
        const __half* src = g_act
                          + ((size_t)((pr >= 0) ? pr : 0) * ID + ck * 32 + c * 8);
        uint32_t dst = sbase + (uint32_t)(r * SAW + c * 8) * 2;
        CP16Z(dst, src, (pr >= 0) ? 16u : 0u);
    }
    #pragma unroll
    for (int it = 0; it < 2; ++it) {
        int s = tid + it * 256;
        int r = s >> 4, c = s & 15;
        const __half* src = dw + (size_t)(ck * 32 + r) * HD + cb * 128 + c * 8;
        uint32_t dst = sbase + BOFF + (uint32_t)(r * SBW + c * 8) * 2;
        CP16(dst, src);
    }
    CP_COMMIT();
}

// ============================ gate+up ============================
// CTA: 128 pairs x (64 gate + 64 up cols). 8 warps (2m x 4n), warp tile 64m x (16g+16u).
__global__ __launch_bounds__(256, 2)
void k_gateup(const float* __restrict__ rw)
{
    const int e = blockIdx.z;
    const int cnt = g_cnt[e];
    const int row0 = blockIdx.y * 128;
    if (row0 >= cnt) return;
    const int cb = blockIdx.x;

    extern __shared__ char smem[];
    __shared__ int sPair[128];
    const uint32_t sbd = smem_to_u32(smem);
    const int tid = threadIdx.x, wid = tid >> 5, lane = tid & 31;
    const int wm = wid >> 2, wn = wid & 3;

    if (tid < 128) {
        int pos = row0 + tid;
        sPair[tid] = (pos < cnt) ? g_pair[e * MAXP + pos] : -1;
    }
    __syncthreads();

    const __half* gw = g_gw + (size_t)e * HD * ID;
    const __half* uw = g_uw + (size_t)e * HD * ID;

    float acc[4][2][2][4];                        // mt, mat(g/u), n8, frag
    #pragma unroll
    for (int i = 0; i < 4; ++i)
        #pragma unroll
        for (int j = 0; j < 2; ++j)
            #pragma unroll
            for (int s = 0; s < 2; ++s)
                #pragma unroll
                for (int q = 0; q < 4; ++q) acc[i][j][s][q] = 0.f;

    gu_issue(0, 0, sbd, sPair, gw, uw, cb, tid);
    gu_issue(1, 1, sbd, sPair, gw, uw, cb, tid);

    const int NCK = HD / 32;
    for (int ck = 0; ck < NCK; ++ck) {
        if (ck < NCK - 1) CP_WAIT1(); else CP_WAIT0();
        __syncthreads();

        const int st = ck % 3;
        uint32_t uA = sbd + st * STAGE;
        uint32_t uB = uA + BOFF;
        #pragma unroll
        for (int ks = 0; ks < 2; ++ks) {
            uint32_t bg[4], bu[4];
            uint32_t brow = (uint32_t)(ks * 16 + (lane & 15));
            uint32_t co   = (uint32_t)((lane >> 4) << 3);
            ldm_x4_t(bg, uB + (brow * SBW + wn * 16 + co) * 2);
            ldm_x4_t(bu, uB + (brow * SBW + 64 + wn * 16 + co) * 2);
            #pragma unroll
            for (int mt = 0; mt < 4; ++mt) {
                uint32_t a[4];
                uint32_t off = (uint32_t)((wm * 64 + mt * 16 + (lane & 15)) * SAW
                                          + ks * 16 + co) * 2;
                ldm_x4(a, uA + off);
                mma16816(acc[mt][0][0], a, bg[0], bg[1]);
                mma16816(acc[mt][0][1], a, bg[2], bg[3]);
                mma16816(acc[mt][1][0], a, bu[0], bu[1]);
                mma16816(acc[mt][1][1], a, bu[2], bu[3]);
            }
        }
        if (ck + 2 < NCK) gu_issue(ck + 2, (ck + 2) % 3, sbd, sPair, gw, uw, cb, tid);
    }

    // epilogue: act = rw * gelu(gate) * up -> fp16 scratch
    #pragma unroll
    for (int mt = 0; mt < 4; ++mt)
        #pragma unroll
        for (int s = 0; s < 2; ++s) {
            int c = cb * 64 + wn * 16 + s * 8 + (lane & 3) * 2;
            #pragma unroll
            for (int half = 0; half < 2; ++half) {
                int r = wm * 64 + mt * 16 + (lane >> 2) + half * 8;
                int pr = sPair[r];
                if (pr < 0) continue;
                float wgt = rw[pr];
                float g0 = acc[mt][0][s][half * 2], g1 = acc[mt][0][s][half * 2 + 1];
                float u0 = acc[mt][1][s][half * 2], u1 = acc[mt][1][s][half * 2 + 1];
                float o0 = wgt * gelu_tanh(g0) * u0;
                float o1 = wgt * gelu_tanh(g1) * u1;
                *(uint32_t*)(g_act + (size_t)pr * ID + c) =
                    pkh(__float2half_rn(o0), __float2half_rn(o1));
            }
        }
}

// ============================ down ============================
// CTA: 128 pairs x 128 hidden cols. 8 warps (2m x 4n), warp tile 64m x 32n.
__global__ __launch_bounds__(256, 2)
void k_down()
{
    const int e = blockIdx.z;
    const int cnt = g_cnt[e];
    const int row0 = blockIdx.y * 128;
    if (row0 >= cnt) return;
    const int cb = blockIdx.x;

    extern __shared__ char smem[];
    __shared__ int sPair[128];
    const uint32_t sbd = smem_to_u32(smem);
    const int tid = threadIdx.x, wid = tid >> 5, lane = tid & 31;
    const int wm = wid >> 2, wn = wid & 3;

    if (tid < 128) {
        int pos = row0 + tid;
        sPair[tid] = (pos < cnt) ? g_pair[e * MAXP + pos] : -1;
    }
    __syncthreads();

    const __half* dw = g_dw + (size_t)e * ID * HD;

    float acc[4][4][4];                           // mt, n8, frag
    #pragma unroll
    for (int i = 0; i < 4; ++i)
        #pragma unroll
        for (int j = 0; j < 4; ++j)
            #pragma unroll
            for (int q = 0; q < 4; ++q) acc[i][j][q] = 0.f;

    dn_issue(0, 0, sbd, sPair, dw, cb, tid);
    dn_issue(1, 1, sbd, sPair, dw, cb, tid);

    const int NCK = ID / 32;
    for (int ck = 0; ck < NCK; ++ck) {
        if (ck < NCK - 1) CP_WAIT1(); else CP_WAIT0();
        __syncthreads();

        const int st = ck % 3;
        uint32_t uA = sbd + st * STAGE;
        uint32_t uB = uA + BOFF;
        #pragma unroll
        for (int ks = 0; ks < 2; ++ks) {
            uint32_t b[8];
            uint32_t brow = (uint32_t)(ks * 16 + (lane & 15));
            uint32_t co   = (uint32_t)((lane >> 4) << 3);
            ldm_x4_t(b,     uB + (brow * SBW + wn * 32 + co) * 2);
            ldm_x4_t(b + 4, uB + (brow * SBW + wn * 32 + 16 + co) * 2);
            #pragma unroll
            for (int mt = 0; mt < 4; ++mt) {
                uint32_t a[4];
                uint32_t off = (uint32_t)((wm * 64 + mt * 16 + (lane & 15)) * SAW
                                          + ks * 16 + co) * 2;
                ldm_x4(a, uA + off);
                mma16816(acc[mt][0], a, b[0], b[1]);
                mma16816(acc[mt][1], a, b[2], b[3]);
                mma16816(acc[mt][2], a, b[4], b[5]);
                mma16816(acc[mt][3], a, b[6], b[7]);
            }
        }
        if (ck + 2 < NCK) dn_issue(ck + 2, (ck + 2) % 3, sbd, sPair, dw, cb, tid);
    }

    // epilogue: per-pair fp32 scratch
    #pragma unroll
    for (int mt = 0; mt < 4; ++mt)
        #pragma unroll
        for (int j = 0; j < 4; ++j) {
            int c = cb * 128 + wn * 32 + j * 8 + (lane & 3) * 2;
            #pragma unroll
            for (int half = 0; half < 2; ++half) {
                int r = wm * 64 + mt * 16 + (lane >> 2) + half * 8;
                int pr = sPair[r];
                if (pr < 0) continue;
                float2 v = make_float2(acc[mt][j][half * 2], acc[mt][j][half * 2 + 1]);
                *(float2*)(g_ds + (size_t)pr * HD + c) = v;
            }
        }
}

// ============================ combine ============================
__global__ void k_combine(float* __restrict__ out) {
    int idx = blockIdx.x * blockDim.x + threadIdx.x;
    int t  = idx >> 9;
    int c4 = idx & 511;
    const float4* s4 = (const float4*)g_ds;
    float4 a = s4[(size_t)(2 * t) * 512 + c4];
    float4 b = s4[(size_t)(2 * t + 1) * 512 + c4];
    ((float4*)out)[idx] = make_float4(a.x + b.x, a.y + b.y, a.z + b.z, a.w + b.w);
}

// ============================ host ============================
extern "C" void kernel_launch(void* const* d_in, const int* in_sizes, int n_in,
                              void* d_out, int out_size)
{
    const float* x      = (const float*)d_in[0];
    const int*   sel    = (const int*)  d_in[1];
    const float* rw     = (const float*)d_in[2];
    const float* gate_w = (const float*)d_in[3];
    const float* up_w   = (const float*)d_in[4];
    const float* down_w = (const float*)d_in[5];
    float* out = (float*)d_out;

    cudaFuncSetAttribute(k_gateup, cudaFuncAttributeMaxDynamicSharedMemorySize, SMEM_SZ);
    cudaFuncSetAttribute(k_down,   cudaFuncAttributeMaxDynamicSharedMemorySize, SMEM_SZ);

    __half *xh, *gw, *uw, *dww;
    cudaGetSymbolAddress((void**)&xh,  g_x_h);
    cudaGetSymbolAddress((void**)&gw,  g_gw);
    cudaGetSymbolAddress((void**)&uw,  g_uw);
    cudaGetSymbolAddress((void**)&dww, g_dw);
    int nx4 = NT * HD / 4;
    int nw4 = NE * HD * ID / 4;

    // launch order puts k_gateup at index 5 so ncu (-s 5 -c 1) profiles it
    k_zero_counts<<<1, 32>>>();                                   // 0
    k_route<<<MAXP / 256, 256>>>(sel);                            // 1
    k_half8<<<(nx4 / 2 + 255) / 256, 256>>>(x, xh, nx4);          // 2
    k_half8<<<(nw4 / 2 + 255) / 256, 256>>>(gate_w, gw, nw4);     // 3
    k_half8<<<(nw4 / 2 + 255) / 256, 256>>>(up_w,   uw, nw4);     // 4

    dim3 g1(ID / 64, MAXP / 128, NE);                             // 5
    k_gateup<<<g1, 256, SMEM_SZ>>>(rw);

    k_half8<<<(nw4 / 2 + 255) / 256, 256>>>(down_w, dww, nw4);    // 6

    dim3 g2(HD / 128, MAXP / 128, NE);                            // 7
    k_down<<<g2, 256, SMEM_SZ>>>();

    k_combine<<<(NT * HD / 4) / 256, 256>>>(out);                 // 8
}

// round 15
// speedup vs baseline: 1.6675x; 1.0301x over previous
#include <cuda_runtime.h>
#include <cuda_fp16.h>
#include <cstdint>
#include <math.h>

#define NE   8
#define HD   2048
#define ID   1024
#define NT   8192
#define TOPK 2
#define MAXP (NT * TOPK)

// smem geometry (fp16 elems), K-chunk = 64
#define SAW    72                    // A row stride: 64 data + 8 pad (144 B; bank step 4 -> ldm ok)
#define SBW    136                   // B row stride: 128 data + 8 pad (272 B)
#define ABYTES (128 * SAW * 2)       // 18432
#define BBYTES (64 * SBW * 2)        // 17408
#define BOFF   ABYTES
#define STAGE  (ABYTES + BBYTES)     // 35840
#define SMEM_SZ (3 * STAGE)          // 107520 -> 2 CTA/SM (210 KB of 228)

// ---- device globals ----
__device__ int    g_cnt[NE];
__device__ int    g_pair[NE * MAXP];
__device__ __half g_x_h[(size_t)NT * HD];
__device__ __half g_gw[(size_t)NE * HD * ID];
__device__ __half g_uw[(size_t)NE * HD * ID];
__device__ __half g_dw[(size_t)NE * ID * HD];
__device__ __half g_act[(size_t)MAXP * ID];
__device__ __half g_ds[(size_t)MAXP * HD];    // 64 MB fp16 per-pair down output

// ============================ asm helpers ============================
__device__ __forceinline__ uint32_t smem_to_u32(const void* p) {
    uint32_t a;
    asm("{ .reg .u64 t; cvta.to.shared.u64 t, %1; cvt.u32.u64 %0, t; }" : "=r"(a) : "l"(p));
    return a;
}
__device__ __forceinline__ void ldm_x4(uint32_t* r, uint32_t a) {
    asm volatile("ldmatrix.sync.aligned.m8n8.x4.shared.b16 {%0,%1,%2,%3}, [%4];"
                 : "=r"(r[0]), "=r"(r[1]), "=r"(r[2]), "=r"(r[3]) : "r"(a));
}
__device__ __forceinline__ void ldm_x4_t(uint32_t* r, uint32_t a) {
    asm volatile("ldmatrix.sync.aligned.m8n8.x4.trans.shared.b16 {%0,%1,%2,%3}, [%4];"
                 : "=r"(r[0]), "=r"(r[1]), "=r"(r[2]), "=r"(r[3]) : "r"(a));
}
__device__ __forceinline__ void mma16816(float* c, const uint32_t* a, uint32_t b0, uint32_t b1) {
    asm volatile("mma.sync.aligned.m16n8k16.row.col.f32.f16.f16.f32 "
                 "{%0,%1,%2,%3}, {%4,%5,%6,%7}, {%8,%9}, {%0,%1,%2,%3};"
                 : "+f"(c[0]), "+f"(c[1]), "+f"(c[2]), "+f"(c[3])
                 : "r"(a[0]), "r"(a[1]), "r"(a[2]), "r"(a[3]), "r"(b0), "r"(b1));
}
#define CP16(dst, src) \
    asm volatile("cp.async.cg.shared.global [%0], [%1], 16;" :: "r"(dst), "l"(src) : "memory")
#define CP16Z(dst, src, n) \
    asm volatile("cp.async.cg.shared.global [%0], [%1], 16, %2;" :: "r"(dst), "l"(src), "r"(n) : "memory")
#define CP_COMMIT() asm volatile("cp.async.commit_group;" ::: "memory")
#define CP_WAIT1()  asm volatile("cp.async.wait_group 1;" ::: "memory")
#define CP_WAIT0()  asm volatile("cp.async.wait_group 0;" ::: "memory")

__device__ __forceinline__ float gelu_tanh(float gv) {
    float t  = gv + 0.044715f * gv * gv * gv;
    float z  = 1.5957691216057308f * t;
    float th = 1.0f - 2.0f / (__expf(z) + 1.0f);
    return 0.5f * gv * (1.0f + th);
}
__device__ __forceinline__ uint32_t pkh(__half a, __half b) {
    __half2 t = __halves2half2(a, b);
    return *reinterpret_cast<uint32_t*>(&t);
}

// ============================ prep kernels ============================
__global__ void k_zero_counts() { if (threadIdx.x < NE) g_cnt[threadIdx.x] = 0; }

__global__ void k_route(const int* __restrict__ sel) {
    int p = blockIdx.x * blockDim.x + threadIdx.x;
    if (p < MAXP) {
        int e = sel[p];
        int pos = atomicAdd(&g_cnt[e], 1);
        g_pair[e * MAXP + pos] = p;
    }
}

__global__ void k_half8(const float* __restrict__ src, __half* __restrict__ dst, int n4) {
    int i = (blockIdx.x * blockDim.x + threadIdx.x) * 2;
    if (i + 1 >= n4) {
        if (i < n4) {
            float4 v = ((const float4*)src)[i];
            __half2 a = __floats2half2_rn(v.x, v.y);
            __half2 b = __floats2half2_rn(v.z, v.w);
            ((uint2*)dst)[i] = make_uint2(*(uint32_t*)&a, *(uint32_t*)&b);
        }
        return;
    }
    float4 v0 = ((const float4*)src)[i];
    float4 v1 = ((const float4*)src)[i + 1];
    __half2 a0 = __floats2half2_rn(v0.x, v0.y), b0 = __floats2half2_rn(v0.z, v0.w);
    __half2 a1 = __floats2half2_rn(v1.x, v1.y), b1 = __floats2half2_rn(v1.z, v1.w);
    ((uint4*)dst)[i >> 1] =
        make_uint4(*(uint32_t*)&a0, *(uint32_t*)&b0, *(uint32_t*)&a1, *(uint32_t*)&b1);
}

// ============================ issue helpers (256 threads, K-chunk 64) ====
// A tile 128x64 fp16: 1024 x16B -> 4 cp/thread. B tile 64x128: 1024 x16B -> 4 cp/thread.
__device__ __forceinline__ void gu_issue(int ck, int st, uint32_t sbd, const int* sPair,
                                         const __half* gw, const __half* uw,
                                         int cb, int tid)
{
    uint32_t sbase = sbd + st * STAGE;
    #pragma unroll
    for (int it = 0; it < 4; ++it) {
        int s = tid + it * 256;
        int r = s >> 3, c = s & 7;
        int pr = sPair[r];
        const __half* src = g_x_h
                          + ((size_t)((pr >= 0) ? (pr >> 1) : 0) * HD + ck * 64 + c * 8);
        uint32_t dst = sbase + (uint32_t)(r * SAW + c * 8) * 2;
        CP16Z(dst, src, (pr >= 0) ? 16u : 0u);
    }
    #pragma unroll
    for (int it = 0; it < 4; ++it) {
        int s = tid + it * 256;
        int r = s >> 4, c = s & 15;               // c: 0..7 gate, 8..15 up
        const __half* w = (c < 8) ? gw : uw;
        const __half* src = w + (size_t)(ck * 64 + r) * ID + cb * 64 + (c & 7) * 8;
        uint32_t dst = sbase + BOFF + (uint32_t)(r * SBW + c * 8) * 2;
        CP16(dst, src);
    }
    CP_COMMIT();
}

__device__ __forceinline__ void dn_issue(int ck, int st, uint32_t sbd, const int* sPair,
                                         const __half* dw, int cb, int tid)
{
    uint32_t sbase = sbd + st * STAGE;
    #pragma unroll
    for (int it = 0; it < 4; ++it) {
        int s = tid + it * 256;
        int r = s >> 3, c = s & 7;
        int pr = sPair[r];
        const __half* src = g_act
                          + ((size_t)((pr >= 0) ? pr : 0) * ID + ck * 64 + c * 8);
        uint32_t dst = sbase + (uint32_t)(r * SAW + c * 8) * 2;
        CP16Z(dst, src, (pr >= 0) ? 16u : 0u);
    }
    #pragma unroll
    for (int it = 0; it < 4; ++it) {
        int s = tid + it * 256;
        int r = s >> 4, c = s & 15;
        const __half* src = dw + (size_t)(ck * 64 + r) * HD + cb * 128 + c * 8;
        uint32_t dst = sbase + BOFF + (uint32_t)(r * SBW + c * 8) * 2;
        CP16(dst, src);
    }
    CP_COMMIT();
}

// ============================ gate+up ============================
// CTA: 128 pairs x (64 gate + 64 up). 8 warps (2m x 4n), warp 64m x (16g+16u).
__global__ __launch_bounds__(256, 2)
void k_gateup(const float* __restrict__ rw)
{
    const int e = blockIdx.z;
    const int cnt = g_cnt[e];
    const int row0 = blockIdx.y * 128;
    if (row0 >= cnt) return;
    const int cb = blockIdx.x;

    extern __shared__ char smem[];
    __shared__ int sPair[128];
    const uint32_t sbd = smem_to_u32(smem);
    const int tid = threadIdx.x, wid = tid >> 5, lane = tid & 31;
    const int wm = wid >> 2, wn = wid & 3;

    if (tid < 128) {
        int pos = row0 + tid;
        sPair[tid] = (pos < cnt) ? g_pair[e * MAXP + pos] : -1;
    }
    __syncthreads();

    const __half* gw = g_gw + (size_t)e * HD * ID;
    const __half* uw = g_uw + (size_t)e * HD * ID;

    float acc[4][2][2][4];
    #pragma unroll
    for (int i = 0; i < 4; ++i)
        #pragma unroll
        for (int j = 0; j < 2; ++j)
            #pragma unroll
            for (int s = 0; s < 2; ++s)
                #pragma unroll
                for (int q = 0; q < 4; ++q) acc[i][j][s][q] = 0.f;

    gu_issue(0, 0, sbd, sPair, gw, uw, cb, tid);
    gu_issue(1, 1, sbd, sPair, gw, uw, cb, tid);

    const int NCK = HD / 64;                      // 32
    for (int ck = 0; ck < NCK; ++ck) {
        if (ck < NCK - 1) CP_WAIT1(); else CP_WAIT0();
        __syncthreads();

        const int st = ck % 3;
        uint32_t uA = sbd + st * STAGE;
        uint32_t uB = uA + BOFF;
        #pragma unroll
        for (int ks = 0; ks < 4; ++ks) {
            uint32_t bg[4], bu[4];
            uint32_t brow = (uint32_t)(ks * 16 + (lane & 15));
            uint32_t co   = (uint32_t)((lane >> 4) << 3);
            ldm_x4_t(bg, uB + (brow * SBW + wn * 16 + co) * 2);
            ldm_x4_t(bu, uB + (brow * SBW + 64 + wn * 16 + co) * 2);
            #pragma unroll
            for (int mt = 0; mt < 4; ++mt) {
                uint32_t a[4];
                uint32_t off = (uint32_t)((wm * 64 + mt * 16 + (lane & 15)) * SAW
                                          + ks * 16 + co) * 2;
                ldm_x4(a, uA + off);
                mma16816(acc[mt][0][0], a, bg[0], bg[1]);
                mma16816(acc[mt][0][1], a, bg[2], bg[3]);
                mma16816(acc[mt][1][0], a, bu[0], bu[1]);
                mma16816(acc[mt][1][1], a, bu[2], bu[3]);
            }
        }
        if (ck + 2 < NCK) gu_issue(ck + 2, (ck + 2) % 3, sbd, sPair, gw, uw, cb, tid);
    }

    // epilogue: act = rw * gelu(gate) * up -> fp16 scratch
    #pragma unroll
    for (int mt = 0; mt < 4; ++mt)
        #pragma unroll
        for (int s = 0; s < 2; ++s) {
            int c = cb * 64 + wn * 16 + s * 8 + (lane & 3) * 2;
            #pragma unroll
            for (int half = 0; half < 2; ++half) {
                int r = wm * 64 + mt * 16 + (lane >> 2) + half * 8;
                int pr = sPair[r];
                if (pr < 0) continue;
                float wgt = rw[pr];
                float g0 = acc[mt][0][s][half * 2], g1 = acc[mt][0][s][half * 2 + 1];
                float u0 = acc[mt][1][s][half * 2], u1 = acc[mt][1][s][half * 2 + 1];
                float o0 = wgt * gelu_tanh(g0) * u0;
                float o1 = wgt * gelu_tanh(g1) * u1;
                *(uint32_t*)(g_act + (size_t)pr * ID + c) =
                    pkh(__float2half_rn(o0), __float2half_rn(o1));
            }
        }
}

// ============================ down ============================
// CTA: 128 pairs x 128 hidden cols. 8 warps (2m x 4n), warp 64m x 32n.
__global__ __launch_bounds__(256, 2)
void k_down()
{
    const int e = blockIdx.z;
    const int cnt = g_cnt[e];
    const int row0 = blockIdx.y * 128;
    if (row0 >= cnt) return;
    const int cb = blockIdx.x;

    extern __shared__ char smem[];
    __shared__ int sPair[128];
    const uint32_t sbd = smem_to_u32(smem);
    const int tid = threadIdx.x, wid = tid >> 5, lane = tid & 31;
    const int wm = wid >> 2, wn = wid & 3;

    if (tid < 128) {
        int pos = row0 + tid;
        sPair[tid] = (pos < cnt) ? g_pair[e * MAXP + pos] : -1;
    }
    __syncthreads();

    const __half* dw = g_dw + (size_t)e * ID * HD;

    float acc[4][4][4];
    #pragma unroll
    for (int i = 0; i < 4; ++i)
        #pragma unroll
        for (int j = 0; j < 4; ++j)
            #pragma unroll
            for (int q = 0; q < 4; ++q) acc[i][j][q] = 0.f;

    dn_issue(0, 0, sbd, sPair, dw, cb, tid);
    dn_issue(1, 1, sbd, sPair, dw, cb, tid);

    const int NCK = ID / 64;                      // 16
    for (int ck = 0; ck < NCK; ++ck) {
        if (ck < NCK - 1) CP_WAIT1(); else CP_WAIT0();
        __syncthreads();

        const int st = ck % 3;
        uint32_t uA = sbd + st * STAGE;
        uint32_t uB = uA + BOFF;
        #pragma unroll
        for (int ks = 0; ks < 4; ++ks) {
            uint32_t b[8];
            uint32_t brow = (uint32_t)(ks * 16 + (lane & 15));
            uint32_t co   = (uint32_t)((lane >> 4) << 3);
            ldm_x4_t(b,     uB + (brow * SBW + wn * 32 + co) * 2);
            ldm_x4_t(b + 4, uB + (brow * SBW + wn * 32 + 16 + co) * 2);
            #pragma unroll
            for (int mt = 0; mt < 4; ++mt) {
                uint32_t a[4];
                uint32_t off = (uint32_t)((wm * 64 + mt * 16 + (lane & 15)) * SAW
                                          + ks * 16 + co) * 2;
                ldm_x4(a, uA + off);
                mma16816(acc[mt][0], a, b[0], b[1]);
                mma16816(acc[mt][1], a, b[2], b[3]);
                mma16816(acc[mt][2], a, b[4], b[5]);
                mma16816(acc[mt][3], a, b[6], b[7]);
            }
        }
        if (ck + 2 < NCK) dn_issue(ck + 2, (ck + 2) % 3, sbd, sPair, dw, cb, tid);
    }

    // epilogue: per-pair fp16 scratch
    #pragma unroll
    for (int mt = 0; mt < 4; ++mt)
        #pragma unroll
        for (int j = 0; j < 4; ++j) {
            int c = cb * 128 + wn * 32 + j * 8 + (lane & 3) * 2;
            #pragma unroll
            for (int half = 0; half < 2; ++half) {
                int r = wm * 64 + mt * 16 + (lane >> 2) + half * 8;
                int pr = sPair[r];
                if (pr < 0) continue;
                *(uint32_t*)(g_ds + (size_t)pr * HD + c) =
                    pkh(__float2half_rn(acc[mt][j][half * 2]),
                        __float2half_rn(acc[mt][j][half * 2 + 1]));
            }
        }
}

// ============================ combine ============================
// out[t] = ds[2t] + ds[2t+1]  (fp16 scratch -> fp32 out), 4 elems/thread
__global__ void k_combine(float* __restrict__ out) {
    int idx = blockIdx.x * blockDim.x + threadIdx.x;   // NT*HD/4 groups
    int t  = idx >> 9;                                 // HD/4 = 512 groups/row
    int c4 = idx & 511;
    const uint2* s2 = (const uint2*)g_ds;              // 4 halves per uint2
    uint2 ua = s2[(size_t)(2 * t) * 512 + c4];
    uint2 ub = s2[(size_t)(2 * t + 1) * 512 + c4];
    __half2 a0 = *(__half2*)&ua.x, a1 = *(__half2*)&ua.y;
    __half2 b0 = *(__half2*)&ub.x, b1 = *(__half2*)&ub.y;
    float2 fa0 = __half22float2(a0), fa1 = __half22float2(a1);
    float2 fb0 = __half22float2(b0), fb1 = __half22float2(b1);
    ((float4*)out)[idx] = make_float4(fa0.x + fb0.x, fa0.y + fb0.y,
                                      fa1.x + fb1.x, fa1.y + fb1.y);
}

// ============================ host ============================
extern "C" void kernel_launch(void* const* d_in, const int* in_sizes, int n_in,
                              void* d_out, int out_size)
{
    const float* x      = (const float*)d_in[0];
    const int*   sel    = (const int*)  d_in[1];
    const float* rw     = (const float*)d_in[2];
    const float* gate_w = (const float*)d_in[3];
    const float* up_w   = (const float*)d_in[4];
    const float* down_w = (const float*)d_in[5];
    float* out = (float*)d_out;

    cudaFuncSetAttribute(k_gateup, cudaFuncAttributeMaxDynamicSharedMemorySize, SMEM_SZ);
    cudaFuncSetAttribute(k_down,   cudaFuncAttributeMaxDynamicSharedMemorySize, SMEM_SZ);

    __half *xh, *gw, *uw, *dww;
    cudaGetSymbolAddress((void**)&xh,  g_x_h);
    cudaGetSymbolAddress((void**)&gw,  g_gw);
    cudaGetSymbolAddress((void**)&uw,  g_uw);
    cudaGetSymbolAddress((void**)&dww, g_dw);
    int nx4 = NT * HD / 4;
    int nw4 = NE * HD * ID / 4;

    // launch order puts k_gateup at index 5 so ncu (-s 5 -c 1) profiles it
    k_zero_counts<<<1, 32>>>();                                   // 0
    k_route<<<MAXP / 256, 256>>>(sel);                            // 1
    k_half8<<<(nx4 / 2 + 255) / 256, 256>>>(x, xh, nx4);          // 2
    k_half8<<<(nw4 / 2 + 255) / 256, 256>>>(gate_w, gw, nw4);     // 3
    k_half8<<<(nw4 / 2 + 255) / 256, 256>>>(up_w,   uw, nw4);     // 4

    dim3 g1(ID / 64, MAXP / 128, NE);                             // 5
    k_gateup<<<g1, 256, SMEM_SZ>>>(rw);

    k_half8<<<(nw4 / 2 + 255) / 256, 256>>>(down_w, dww, nw4);    // 6

    dim3 g2(HD / 128, MAXP / 128, NE);                            // 7
    k_down<<<g2, 256, SMEM_SZ>>>();

    k_combine<<<(NT * HD / 4) / 256, 256>>>(out);                 // 8
}

// round 16
// speedup vs baseline: 1.6731x; 1.0034x over previous
#include <cuda_runtime.h>
#include <cuda_fp16.h>
#include <cstdint>
#include <math.h>

#define NE   8
#define HD   2048
#define ID   1024
#define NT   8192
#define TOPK 2
#define MAXP (NT * TOPK)

// smem geometry (fp16 elems), K-chunk = 64
#define SAW    72                    // A row stride: 64 data + 8 pad (144 B)
#define SBW    136                   // B row stride: 128 data + 8 pad (272 B)
#define ABYTES (128 * SAW * 2)       // 18432
#define BBYTES (64 * SBW * 2)        // 17408
#define BOFF   ABYTES
#define STAGE  (ABYTES + BBYTES)     // 35840
#define SMEM_SZ (3 * STAGE)          // 107520 -> 2 CTA/SM

// ---- device globals ----
__device__ int    g_cnt[NE];
__device__ int    g_pair[NE * MAXP];
__device__ __half g_x_h[(size_t)NT * HD];
__device__ __half g_gw[(size_t)NE * HD * ID];
__device__ __half g_uw[(size_t)NE * HD * ID];
__device__ __half g_dw[(size_t)NE * ID * HD];
__device__ __half g_act[(size_t)MAXP * ID];
__device__ __half g_ds[(size_t)MAXP * HD];

// ============================ asm helpers ============================
__device__ __forceinline__ uint32_t smem_to_u32(const void* p) {
    uint32_t a;
    asm("{ .reg .u64 t; cvta.to.shared.u64 t, %1; cvt.u32.u64 %0, t; }" : "=r"(a) : "l"(p));
    return a;
}
__device__ __forceinline__ void ldm_x4(uint32_t* r, uint32_t a) {
    asm volatile("ldmatrix.sync.aligned.m8n8.x4.shared.b16 {%0,%1,%2,%3}, [%4];"
                 : "=r"(r[0]), "=r"(r[1]), "=r"(r[2]), "=r"(r[3]) : "r"(a));
}
__device__ __forceinline__ void ldm_x4_t(uint32_t* r, uint32_t a) {
    asm volatile("ldmatrix.sync.aligned.m8n8.x4.trans.shared.b16 {%0,%1,%2,%3}, [%4];"
                 : "=r"(r[0]), "=r"(r[1]), "=r"(r[2]), "=r"(r[3]) : "r"(a));
}
__device__ __forceinline__ void mma16816(float* c, const uint32_t* a, uint32_t b0, uint32_t b1) {
    asm volatile("mma.sync.aligned.m16n8k16.row.col.f32.f16.f16.f32 "
                 "{%0,%1,%2,%3}, {%4,%5,%6,%7}, {%8,%9}, {%0,%1,%2,%3};"
                 : "+f"(c[0]), "+f"(c[1]), "+f"(c[2]), "+f"(c[3])
                 : "r"(a[0]), "r"(a[1]), "r"(a[2]), "r"(a[3]), "r"(b0), "r"(b1));
}
#define CP16(dst, src) \
    asm volatile("cp.async.cg.shared.global [%0], [%1], 16;" :: "r"(dst), "l"(src) : "memory")
#define CP16Z(dst, src, n) \
    asm volatile("cp.async.cg.shared.global [%0], [%1], 16, %2;" :: "r"(dst), "l"(src), "r"(n) : "memory")
#define CP_COMMIT() asm volatile("cp.async.commit_group;" ::: "memory")
#define CP_WAIT1()  asm volatile("cp.async.wait_group 1;" ::: "memory")
#define CP_WAIT0()  asm volatile("cp.async.wait_group 0;" ::: "memory")

__device__ __forceinline__ float gelu_tanh(float gv) {
    float t  = gv + 0.044715f * gv * gv * gv;
    float z  = 1.5957691216057308f * t;
    float th = 1.0f - 2.0f / (__expf(z) + 1.0f);
    return 0.5f * gv * (1.0f + th);
}
__device__ __forceinline__ uint32_t pkh(__half a, __half b) {
    __half2 t = __halves2half2(a, b);
    return *reinterpret_cast<uint32_t*>(&t);
}

// ============================ prep kernels ============================
__global__ void k_zero_counts() { if (threadIdx.x < NE) g_cnt[threadIdx.x] = 0; }

__global__ void k_route(const int* __restrict__ sel) {
    int p = blockIdx.x * blockDim.x + threadIdx.x;
    if (p < MAXP) {
        int e = sel[p];
        int pos = atomicAdd(&g_cnt[e], 1);
        g_pair[e * MAXP + pos] = p;
    }
}

__global__ void k_half8(const float* __restrict__ src, __half* __restrict__ dst, int n4) {
    int i = (blockIdx.x * blockDim.x + threadIdx.x) * 2;
    if (i + 1 >= n4) {
        if (i < n4) {
            float4 v = ((const float4*)src)[i];
            __half2 a = __floats2half2_rn(v.x, v.y);
            __half2 b = __floats2half2_rn(v.z, v.w);
            ((uint2*)dst)[i] = make_uint2(*(uint32_t*)&a, *(uint32_t*)&b);
        }
        return;
    }
    float4 v0 = ((const float4*)src)[i];
    float4 v1 = ((const float4*)src)[i + 1];
    __half2 a0 = __floats2half2_rn(v0.x, v0.y), b0 = __floats2half2_rn(v0.z, v0.w);
    __half2 a1 = __floats2half2_rn(v1.x, v1.y), b1 = __floats2half2_rn(v1.z, v1.w);
    ((uint4*)dst)[i >> 1] =
        make_uint4(*(uint32_t*)&a0, *(uint32_t*)&b0, *(uint32_t*)&a1, *(uint32_t*)&b1);
}

// ============================ issue helpers (256 threads, K-chunk 64) ====
__device__ __forceinline__ void gu_issue(int ck, int st, uint32_t sbd, const int* sPair,
                                         const __half* gw, const __half* uw,
                                         int cb, int tid)
{
    uint32_t sbase = sbd + st * STAGE;
    #pragma unroll
    for (int it = 0; it < 4; ++it) {
        int s = tid + it * 256;
        int r = s >> 3, c = s & 7;
        int pr = sPair[r];
        const __half* src = g_x_h
                          + ((size_t)((pr >= 0) ? (pr >> 1) : 0) * HD + ck * 64 + c * 8);
        uint32_t dst = sbase + (uint32_t)(r * SAW + c * 8) * 2;
        CP16Z(dst, src, (pr >= 0) ? 16u : 0u);
    }
    #pragma unroll
    for (int it = 0; it < 4; ++it) {
        int s = tid + it * 256;
        int r = s >> 4, c = s & 15;               // c: 0..7 gate, 8..15 up
        const __half* w = (c < 8) ? gw : uw;
        const __half* src = w + (size_t)(ck * 64 + r) * ID + cb * 64 + (c & 7) * 8;
        uint32_t dst = sbase + BOFF + (uint32_t)(r * SBW + c * 8) * 2;
        CP16(dst, src);
    }
    CP_COMMIT();
}

__device__ __forceinline__ void dn_issue(int ck, int st, uint32_t sbd, const int* sPair,
                                         const __half* dw, int cb, int tid)
{
    uint32_t sbase = sbd + st * STAGE;
    #pragma unroll
    for (int it = 0; it < 4; ++it) {
        int s = tid + it * 256;
        int r = s >> 3, c = s & 7;
        int pr = sPair[r];
        const __half* src = g_act
                          + ((size_t)((pr >= 0) ? pr : 0) * ID + ck * 64 + c * 8);
        uint32_t dst = sbase + (uint32_t)(r * SAW + c * 8) * 2;
        CP16Z(dst, src, (pr >= 0) ? 16u : 0u);
    }
    #pragma unroll
    for (int it = 0; it < 4; ++it) {
        int s = tid + it * 256;
        int r = s >> 4, c = s & 15;
        const __half* src = dw + (size_t)(ck * 64 + r) * HD + cb * 128 + c * 8;
        uint32_t dst = sbase + BOFF + (uint32_t)(r * SBW + c * 8) * 2;
        CP16(dst, src);
    }
    CP_COMMIT();
}

// ============================ gate+up ============================
// CTA: 128 pairs x (64 gate + 64 up). 8 warps (2m x 4n), warp 64m x (16g+16u).
// ks-step: batch 6 LDSMs (2 B + 4 A) before the 16 MMAs (MLP for LDS latency).
__global__ __launch_bounds__(256, 2)
void k_gateup(const float* __restrict__ rw)
{
    const int e = blockIdx.z;
    const int cnt = g_cnt[e];
    const int row0 = blockIdx.y * 128;
    if (row0 >= cnt) return;
    const int cb = blockIdx.x;

    extern __shared__ char smem[];
    __shared__ int sPair[128];
    const uint32_t sbd = smem_to_u32(smem);
    const int tid = threadIdx.x, wid = tid >> 5, lane = tid & 31;
    const int wm = wid >> 2, wn = wid & 3;

    if (tid < 128) {
        int pos = row0 + tid;
        sPair[tid] = (pos < cnt) ? g_pair[e * MAXP + pos] : -1;
    }
    __syncthreads();

    const __half* gw = g_gw + (size_t)e * HD * ID;
    const __half* uw = g_uw + (size_t)e * HD * ID;

    float acc[4][2][2][4];
    #pragma unroll
    for (int i = 0; i < 4; ++i)
        #pragma unroll
        for (int j = 0; j < 2; ++j)
            #pragma unroll
            for (int s = 0; s < 2; ++s)
                #pragma unroll
                for (int q = 0; q < 4; ++q) acc[i][j][s][q] = 0.f;

    gu_issue(0, 0, sbd, sPair, gw, uw, cb, tid);
    gu_issue(1, 1, sbd, sPair, gw, uw, cb, tid);

    const int NCK = HD / 64;                      // 32
    for (int ck = 0; ck < NCK; ++ck) {
        if (ck < NCK - 1) CP_WAIT1(); else CP_WAIT0();
        __syncthreads();

        const int st = ck % 3;
        uint32_t uA = sbd + st * STAGE;
        uint32_t uB = uA + BOFF;
        #pragma unroll
        for (int ks = 0; ks < 4; ++ks) {
            uint32_t bg[4], bu[4], a[4][4];
            uint32_t brow = (uint32_t)(ks * 16 + (lane & 15));
            uint32_t co   = (uint32_t)((lane >> 4) << 3);
            ldm_x4_t(bg, uB + (brow * SBW + wn * 16 + co) * 2);
            ldm_x4_t(bu, uB + (brow * SBW + 64 + wn * 16 + co) * 2);
            #pragma unroll
            for (int mt = 0; mt < 4; ++mt) {
                uint32_t off = (uint32_t)((wm * 64 + mt * 16 + (lane & 15)) * SAW
                                          + ks * 16 + co) * 2;
                ldm_x4(a[mt], uA + off);
            }
            #pragma unroll
            for (int mt = 0; mt < 4; ++mt) {
                mma16816(acc[mt][0][0], a[mt], bg[0], bg[1]);
                mma16816(acc[mt][0][1], a[mt], bg[2], bg[3]);
                mma16816(acc[mt][1][0], a[mt], bu[0], bu[1]);
                mma16816(acc[mt][1][1], a[mt], bu[2], bu[3]);
            }
        }
        if (ck + 2 < NCK) gu_issue(ck + 2, (ck + 2) % 3, sbd, sPair, gw, uw, cb, tid);
    }

    // epilogue: act = rw * gelu(gate) * up -> fp16 scratch
    #pragma unroll
    for (int mt = 0; mt < 4; ++mt)
        #pragma unroll
        for (int s = 0; s < 2; ++s) {
            int c = cb * 64 + wn * 16 + s * 8 + (lane & 3) * 2;
            #pragma unroll
            for (int half = 0; half < 2; ++half) {
                int r = wm * 64 + mt * 16 + (lane >> 2) + half * 8;
                int pr = sPair[r];
                if (pr < 0) continue;
                float wgt = rw[pr];
                float g0 = acc[mt][0][s][half * 2], g1 = acc[mt][0][s][half * 2 + 1];
                float u0 = acc[mt][1][s][half * 2], u1 = acc[mt][1][s][half * 2 + 1];
                float o0 = wgt * gelu_tanh(g0) * u0;
                float o1 = wgt * gelu_tanh(g1) * u1;
                *(uint32_t*)(g_act + (size_t)pr * ID + c) =
                    pkh(__float2half_rn(o0), __float2half_rn(o1));
            }
        }
}

// ============================ down ============================
// CTA: 128 pairs x 128 hidden cols. 8 warps (2m x 4n), warp 64m x 32n.
__global__ __launch_bounds__(256, 2)
void k_down()
{
    const int e = blockIdx.z;
    const int cnt = g_cnt[e];
    const int row0 = blockIdx.y * 128;
    if (row0 >= cnt) return;
    const int cb = blockIdx.x;

    extern __shared__ char smem[];
    __shared__ int sPair[128];
    const uint32_t sbd = smem_to_u32(smem);
    const int tid = threadIdx.x, wid = tid >> 5, lane = tid & 31;
    const int wm = wid >> 2, wn = wid & 3;

    if (tid < 128) {
        int pos = row0 + tid;
        sPair[tid] = (pos < cnt) ? g_pair[e * MAXP + pos] : -1;
    }
    __syncthreads();

    const __half* dw = g_dw + (size_t)e * ID * HD;

    float acc[4][4][4];
    #pragma unroll
    for (int i = 0; i < 4; ++i)
        #pragma unroll
        for (int j = 0; j < 4; ++j)
            #pragma unroll
            for (int q = 0; q < 4; ++q) acc[i][j][q] = 0.f;

    dn_issue(0, 0, sbd, sPair, dw, cb, tid);
    dn_issue(1, 1, sbd, sPair, dw, cb, tid);

    const int NCK = ID / 64;                      // 16
    for (int ck = 0; ck < NCK; ++ck) {
        if (ck < NCK - 1) CP_WAIT1(); else CP_WAIT0();
        __syncthreads();

        const int st = ck % 3;
        uint32_t uA = sbd + st * STAGE;
        uint32_t uB = uA + BOFF;
        #pragma unroll
        for (int ks = 0; ks < 4; ++ks) {
            uint32_t b[8], a[4][4];
            uint32_t brow = (uint32_t)(ks * 16 + (lane & 15));
            uint32_t co   = (uint32_t)((lane >> 4) << 3);
            ldm_x4_t(b,     uB + (brow * SBW + wn * 32 + co) * 2);
            ldm_x4_t(b + 4, uB + (brow * SBW + wn * 32 + 16 + co) * 2);
            #pragma unroll
            for (int mt = 0; mt < 4; ++mt) {
                uint32_t off = (uint32_t)((wm * 64 + mt * 16 + (lane & 15)) * SAW
                                          + ks * 16 + co) * 2;
                ldm_x4(a[mt], uA + off);
            }
            #pragma unroll
            for (int mt = 0; mt < 4; ++mt) {
                mma16816(acc[mt][0], a[mt], b[0], b[1]);
                mma16816(acc[mt][1], a[mt], b[2], b[3]);
                mma16816(acc[mt][2], a[mt], b[4], b[5]);
                mma16816(acc[mt][3], a[mt], b[6], b[7]);
            }
        }
        if (ck + 2 < NCK) dn_issue(ck + 2, (ck + 2) % 3, sbd, sPair, dw, cb, tid);
    }

    // epilogue: per-pair fp16 scratch
    #pragma unroll
    for (int mt = 0; mt < 4; ++mt)
        #pragma unroll
        for (int j = 0; j < 4; ++j) {
            int c = cb * 128 + wn * 32 + j * 8 + (lane & 3) * 2;
            #pragma unroll
            for (int half = 0; half < 2; ++half) {
                int r = wm * 64 + mt * 16 + (lane >> 2) + half * 8;
                int pr = sPair[r];
                if (pr < 0) continue;
                *(uint32_t*)(g_ds + (size_t)pr * HD + c) =
                    pkh(__float2half_rn(acc[mt][j][half * 2]),
                        __float2half_rn(acc[mt][j][half * 2 + 1]));
            }
        }
}

// ============================ combine ============================
__global__ void k_combine(float* __restrict__ out) {
    int idx = blockIdx.x * blockDim.x + threadIdx.x;
    int t  = idx >> 9;
    int c4 = idx & 511;
    const uint2* s2 = (const uint2*)g_ds;
    uint2 ua = s2[(size_t)(2 * t) * 512 + c4];
    uint2 ub = s2[(size_t)(2 * t + 1) * 512 + c4];
    __half2 a0 = *(__half2*)&ua.x, a1 = *(__half2*)&ua.y;
    __half2 b0 = *(__half2*)&ub.x, b1 = *(__half2*)&ub.y;
    float2 fa0 = __half22float2(a0), fa1 = __half22float2(a1);
    float2 fb0 = __half22float2(b0), fb1 = __half22float2(b1);
    ((float4*)out)[idx] = make_float4(fa0.x + fb0.x, fa0.y + fb0.y,
                                      fa1.x + fb1.x, fa1.y + fb1.y);
}

// ============================ host ============================
extern "C" void kernel_launch(void* const* d_in, const int* in_sizes, int n_in,
                              void* d_out, int out_size)
{
    const float* x      = (const float*)d_in[0];
    const int*   sel    = (const int*)  d_in[1];
    const float* rw     = (const float*)d_in[2];
    const float* gate_w = (const float*)d_in[3];
    const float* up_w   = (const float*)d_in[4];
    const float* down_w = (const float*)d_in[5];
    float* out = (float*)d_out;

    cudaFuncSetAttribute(k_gateup, cudaFuncAttributeMaxDynamicSharedMemorySize, SMEM_SZ);
    cudaFuncSetAttribute(k_down,   cudaFuncAttributeMaxDynamicSharedMemorySize, SMEM_SZ);

    __half *xh, *gw, *uw, *dww;
    cudaGetSymbolAddress((void**)&xh,  g_x_h);
    cudaGetSymbolAddress((void**)&gw,  g_gw);
    cudaGetSymbolAddress((void**)&uw,  g_uw);
    cudaGetSymbolAddress((void**)&dww, g_dw);
    int nx4 = NT * HD / 4;
    int nw4 = NE * HD * ID / 4;

    k_zero_counts<<<1, 32>>>();                                   // 0
    k_route<<<MAXP / 256, 256>>>(sel);                            // 1
    k_half8<<<(nx4 / 2 + 255) / 256, 256>>>(x, xh, nx4);          // 2
    k_half8<<<(nw4 / 2 + 255) / 256, 256>>>(gate_w, gw, nw4);     // 3
    k_half8<<<(nw4 / 2 + 255) / 256, 256>>>(up_w,   uw, nw4);     // 4

    dim3 g1(ID / 64, MAXP / 128, NE);                             // 5
    k_gateup<<<g1, 256, SMEM_SZ>>>(rw);

    k_half8<<<(nw4 / 2 + 255) / 256, 256>>>(down_w, dww, nw4);    // 6

    dim3 g2(HD / 128, MAXP / 128, NE);                            // 7
    k_down<<<g2, 256, SMEM_SZ>>>();

    k_combine<<<(NT * HD / 4) / 256, 256>>>(out);                 // 8
}

// round 17
// speedup vs baseline: 1.6732x; 1.0000x over previous
#include <cuda_runtime.h>
#include <cuda_fp16.h>
#include <cstdint>
#include <math.h>

#define NE   8
#define HD   2048
#define ID   1024
#define NT   8192
#define TOPK 2
#define MAXP (NT * TOPK)

// smem geometry (fp16 elems), K-chunk = 64
#define SAW    72                    // A row stride: 64 data + 8 pad (144 B)
#define SBW    136                   // B row stride: 128 data + 8 pad (272 B)
#define ABYTES (128 * SAW * 2)       // 18432
#define BBYTES (64 * SBW * 2)        // 17408
#define BOFF   ABYTES
#define STAGE  (ABYTES + BBYTES)     // 35840
#define SMEM_SZ (3 * STAGE)          // 107520 -> 2 CTA/SM

// ---- device globals ----
__device__ int    g_cnt[NE];
__device__ int    g_pair[NE * MAXP];
__device__ __half g_x_h[(size_t)NT * HD];
__device__ __half g_gw[(size_t)NE * HD * ID];
__device__ __half g_uw[(size_t)NE * HD * ID];
__device__ __half g_dw[(size_t)NE * ID * HD];
__device__ __half g_act[(size_t)MAXP * ID];
__device__ __half g_ds[(size_t)MAXP * HD];

// ============================ asm helpers ============================
__device__ __forceinline__ uint32_t smem_to_u32(const void* p) {
    uint32_t a;
    asm("{ .reg .u64 t; cvta.to.shared.u64 t, %1; cvt.u32.u64 %0, t; }" : "=r"(a) : "l"(p));
    return a;
}
__device__ __forceinline__ void ldm_x4(uint32_t* r, uint32_t a) {
    asm volatile("ldmatrix.sync.aligned.m8n8.x4.shared.b16 {%0,%1,%2,%3}, [%4];"
                 : "=r"(r[0]), "=r"(r[1]), "=r"(r[2]), "=r"(r[3]) : "r"(a));
}
__device__ __forceinline__ void ldm_x4_t(uint32_t* r, uint32_t a) {
    asm volatile("ldmatrix.sync.aligned.m8n8.x4.trans.shared.b16 {%0,%1,%2,%3}, [%4];"
                 : "=r"(r[0]), "=r"(r[1]), "=r"(r[2]), "=r"(r[3]) : "r"(a));
}
__device__ __forceinline__ void mma16816(float* c, const uint32_t* a, uint32_t b0, uint32_t b1) {
    asm volatile("mma.sync.aligned.m16n8k16.row.col.f32.f16.f16.f32 "
                 "{%0,%1,%2,%3}, {%4,%5,%6,%7}, {%8,%9}, {%0,%1,%2,%3};"
                 : "+f"(c[0]), "+f"(c[1]), "+f"(c[2]), "+f"(c[3])
                 : "r"(a[0]), "r"(a[1]), "r"(a[2]), "r"(a[3]), "r"(b0), "r"(b1));
}
#define CP16(dst, src) \
    asm volatile("cp.async.cg.shared.global [%0], [%1], 16;" :: "r"(dst), "l"(src) : "memory")
#define CP16Z(dst, src, n) \
    asm volatile("cp.async.cg.shared.global [%0], [%1], 16, %2;" :: "r"(dst), "l"(src), "r"(n) : "memory")
#define CP_COMMIT() asm volatile("cp.async.commit_group;" ::: "memory")
#define CP_WAIT1()  asm volatile("cp.async.wait_group 1;" ::: "memory")
#define CP_WAIT0()  asm volatile("cp.async.wait_group 0;" ::: "memory")

__device__ __forceinline__ float gelu_tanh(float gv) {
    float t  = gv + 0.044715f * gv * gv * gv;
    float z  = 1.5957691216057308f * t;
    float th = 1.0f - 2.0f / (__expf(z) + 1.0f);
    return 0.5f * gv * (1.0f + th);
}
__device__ __forceinline__ uint32_t pkh(__half a, __half b) {
    __half2 t = __halves2half2(a, b);
    return *reinterpret_cast<uint32_t*>(&t);
}

// ============================ prep kernels ============================
__global__ void k_zero_counts() { if (threadIdx.x < NE) g_cnt[threadIdx.x] = 0; }

__global__ void k_route(const int* __restrict__ sel) {
    int p = blockIdx.x * blockDim.x + threadIdx.x;
    if (p < MAXP) {
        int e = sel[p];
        int pos = atomicAdd(&g_cnt[e], 1);
        g_pair[e * MAXP + pos] = p;
    }
}

__global__ void k_half8(const float* __restrict__ src, __half* __restrict__ dst, int n4) {
    int i = (blockIdx.x * blockDim.x + threadIdx.x) * 2;
    if (i + 1 >= n4) {
        if (i < n4) {
            float4 v = ((const float4*)src)[i];
            __half2 a = __floats2half2_rn(v.x, v.y);
            __half2 b = __floats2half2_rn(v.z, v.w);
            ((uint2*)dst)[i] = make_uint2(*(uint32_t*)&a, *(uint32_t*)&b);
        }
        return;
    }
    float4 v0 = ((const float4*)src)[i];
    float4 v1 = ((const float4*)src)[i + 1];
    __half2 a0 = __floats2half2_rn(v0.x, v0.y), b0 = __floats2half2_rn(v0.z, v0.w);
    __half2 a1 = __floats2half2_rn(v1.x, v1.y), b1 = __floats2half2_rn(v1.z, v1.w);
    ((uint4*)dst)[i >> 1] =
        make_uint4(*(uint32_t*)&a0, *(uint32_t*)&b0, *(uint32_t*)&a1, *(uint32_t*)&b1);
}

// ============================ issue helpers (256 threads, K-chunk 64) ====
__device__ __forceinline__ void gu_issue(int ck, int st, uint32_t sbd, const int* sPair,
                                         const __half* gw, const __half* uw,
                                         int cb, int tid)
{
    uint32_t sbase = sbd + st * STAGE;
    #pragma unroll
    for (int it = 0; it < 4; ++it) {
        int s = tid + it * 256;
        int r = s >> 3, c = s & 7;
        int pr = sPair[r];
        const __half* src = g_x_h
                          + ((size_t)((pr >= 0) ? (pr >> 1) : 0) * HD + ck * 64 + c * 8);
        uint32_t dst = sbase + (uint32_t)(r * SAW + c * 8) * 2;
        CP16Z(dst, src, (pr >= 0) ? 16u : 0u);
    }
    #pragma unroll
    for (int it = 0; it < 4; ++it) {
        int s = tid + it * 256;
        int r = s >> 4, c = s & 15;               // c: 0..7 gate, 8..15 up
        const __half* w = (c < 8) ? gw : uw;
        const __half* src = w + (size_t)(ck * 64 + r) * ID + cb * 64 + (c & 7) * 8;
        uint32_t dst = sbase + BOFF + (uint32_t)(r * SBW + c * 8) * 2;
        CP16(dst, src);
    }
    CP_COMMIT();
}

__device__ __forceinline__ void dn_issue(int ck, int st, uint32_t sbd, const int* sPair,
                                         const __half* dw, int cb, int tid)
{
    uint32_t sbase = sbd + st * STAGE;
    #pragma unroll
    for (int it = 0; it < 4; ++it) {
        int s = tid + it * 256;
        int r = s >> 3, c = s & 7;
        int pr = sPair[r];
        const __half* src = g_act
                          + ((size_t)((pr >= 0) ? pr : 0) * ID + ck * 64 + c * 8);
        uint32_t dst = sbase + (uint32_t)(r * SAW + c * 8) * 2;
        CP16Z(dst, src, (pr >= 0) ? 16u : 0u);
    }
    #pragma unroll
    for (int it = 0; it < 4; ++it) {
        int s = tid + it * 256;
        int r = s >> 4, c = s & 15;
        const __half* src = dw + (size_t)(ck * 64 + r) * HD + cb * 128 + c * 8;
        uint32_t dst = sbase + BOFF + (uint32_t)(r * SBW + c * 8) * 2;
        CP16(dst, src);
    }
    CP_COMMIT();
}

// ============================ gate+up ============================
// CTA: 128 pairs x (64 gate + 64 up). 8 warps (2m x 4n), warp 64m x (16g+16u).
// Inner loop software-pipelined: B double-buffered across ks, A rotating 2-slot
// buffer so each A-LDSM's latency hides under the previous mt's MMA issue burst.
__global__ __launch_bounds__(256, 2)
void k_gateup(const float* __restrict__ rw)
{
    const int e = blockIdx.z;
    const int cnt = g_cnt[e];
    const int row0 = blockIdx.y * 128;
    if (row0 >= cnt) return;
    const int cb = blockIdx.x;

    extern __shared__ char smem[];
    __shared__ int sPair[128];
    const uint32_t sbd = smem_to_u32(smem);
    const int tid = threadIdx.x, wid = tid >> 5, lane = tid & 31;
    const int wm = wid >> 2, wn = wid & 3;

    if (tid < 128) {
        int pos = row0 + tid;
        sPair[tid] = (pos < cnt) ? g_pair[e * MAXP + pos] : -1;
    }
    __syncthreads();

    const __half* gw = g_gw + (size_t)e * HD * ID;
    const __half* uw = g_uw + (size_t)e * HD * ID;

    float acc[4][2][2][4];
    #pragma unroll
    for (int i = 0; i < 4; ++i)
        #pragma unroll
        for (int j = 0; j < 2; ++j)
            #pragma unroll
            for (int s = 0; s < 2; ++s)
                #pragma unroll
                for (int q = 0; q < 4; ++q) acc[i][j][s][q] = 0.f;

    gu_issue(0, 0, sbd, sPair, gw, uw, cb, tid);
    gu_issue(1, 1, sbd, sPair, gw, uw, cb, tid);

    const uint32_t co    = (uint32_t)((lane >> 4) << 3);
    const uint32_t arow  = (uint32_t)(wm * 64 + (lane & 15));
    const uint32_t brow0 = (uint32_t)(lane & 15);

    const int NCK = HD / 64;                      // 32
    for (int ck = 0; ck < NCK; ++ck) {
        if (ck < NCK - 1) CP_WAIT1(); else CP_WAIT0();
        __syncthreads();

        const int st = ck % 3;
        uint32_t uA = sbd + st * STAGE;
        uint32_t uB = uA + BOFF;

        uint32_t bg[2][4], bu[2][4], a2[2][4];
        // preload B for ks=0
        ldm_x4_t(bg[0], uB + ((brow0) * SBW + wn * 16 + co) * 2);
        ldm_x4_t(bu[0], uB + ((brow0) * SBW + 64 + wn * 16 + co) * 2);
        #pragma unroll
        for (int ks = 0; ks < 4; ++ks) {
            const int cur = ks & 1, nxt = cur ^ 1;
            // preload A for mt=0
            ldm_x4(a2[0], uA + ((arow) * SAW + ks * 16 + co) * 2);
            // preload B for ks+1 (overlaps with this ks's MMAs)
            if (ks < 3) {
                uint32_t brow = (uint32_t)((ks + 1) * 16) + brow0;
                ldm_x4_t(bg[nxt], uB + (brow * SBW + wn * 16 + co) * 2);
                ldm_x4_t(bu[nxt], uB + (brow * SBW + 64 + wn * 16 + co) * 2);
            }
            #pragma unroll
            for (int mt = 0; mt < 4; ++mt) {
                if (mt < 3)
                    ldm_x4(a2[(mt + 1) & 1],
                           uA + ((arow + (mt + 1) * 16) * SAW + ks * 16 + co) * 2);
                const uint32_t* am = a2[mt & 1];
                mma16816(acc[mt][0][0], am, bg[cur][0], bg[cur][1]);
                mma16816(acc[mt][0][1], am, bg[cur][2], bg[cur][3]);
                mma16816(acc[mt][1][0], am, bu[cur][0], bu[cur][1]);
                mma16816(acc[mt][1][1], am, bu[cur][2], bu[cur][3]);
            }
        }
        if (ck + 2 < NCK) gu_issue(ck + 2, (ck + 2) % 3, sbd, sPair, gw, uw, cb, tid);
    }

    // epilogue: act = rw * gelu(gate) * up -> fp16 scratch
    #pragma unroll
    for (int mt = 0; mt < 4; ++mt)
        #pragma unroll
        for (int s = 0; s < 2; ++s) {
            int c = cb * 64 + wn * 16 + s * 8 + (lane & 3) * 2;
            #pragma unroll
            for (int half = 0; half < 2; ++half) {
                int r = wm * 64 + mt * 16 + (lane >> 2) + half * 8;
                int pr = sPair[r];
                if (pr < 0) continue;
                float wgt = rw[pr];
                float g0 = acc[mt][0][s][half * 2], g1 = acc[mt][0][s][half * 2 + 1];
                float u0 = acc[mt][1][s][half * 2], u1 = acc[mt][1][s][half * 2 + 1];
                float o0 = wgt * gelu_tanh(g0) * u0;
                float o1 = wgt * gelu_tanh(g1) * u1;
                *(uint32_t*)(g_act + (size_t)pr * ID + c) =
                    pkh(__float2half_rn(o0), __float2half_rn(o1));
            }
        }
}

// ============================ down ============================
// CTA: 128 pairs x 128 hidden cols. 8 warps (2m x 4n), warp 64m x 32n.
__global__ __launch_bounds__(256, 2)
void k_down()
{
    const int e = blockIdx.z;
    const int cnt = g_cnt[e];
    const int row0 = blockIdx.y * 128;
    if (row0 >= cnt) return;
    const int cb = blockIdx.x;

    extern __shared__ char smem[];
    __shared__ int sPair[128];
    const uint32_t sbd = smem_to_u32(smem);
    const int tid = threadIdx.x, wid = tid >> 5, lane = tid & 31;
    const int wm = wid >> 2, wn = wid & 3;

    if (tid < 128) {
        int pos = row0 + tid;
        sPair[tid] = (pos < cnt) ? g_pair[e * MAXP + pos] : -1;
    }
    __syncthreads();

    const __half* dw = g_dw + (size_t)e * ID * HD;

    float acc[4][4][4];
    #pragma unroll
    for (int i = 0; i < 4; ++i)
        #pragma unroll
        for (int j = 0; j < 4; ++j)
            #pragma unroll
            for (int q = 0; q < 4; ++q) acc[i][j][q] = 0.f;

    dn_issue(0, 0, sbd, sPair, dw, cb, tid);
    dn_issue(1, 1, sbd, sPair, dw, cb, tid);

    const uint32_t co    = (uint32_t)((lane >> 4) << 3);
    const uint32_t arow  = (uint32_t)(wm * 64 + (lane & 15));
    const uint32_t brow0 = (uint32_t)(lane & 15);

    const int NCK = ID / 64;                      // 16
    for (int ck = 0; ck < NCK; ++ck) {
        if (ck < NCK - 1) CP_WAIT1(); else CP_WAIT0();
        __syncthreads();

        const int st = ck % 3;
        uint32_t uA = sbd + st * STAGE;
        uint32_t uB = uA + BOFF;

        uint32_t b2[2][8], a2[2][4];
        ldm_x4_t(b2[0],     uB + (brow0 * SBW + wn * 32 + co) * 2);
        ldm_x4_t(b2[0] + 4, uB + (brow0 * SBW + wn * 32 + 16 + co) * 2);
        #pragma unroll
        for (int ks = 0; ks < 4; ++ks) {
            const int cur = ks & 1, nxt = cur ^ 1;
            ldm_x4(a2[0], uA + (arow * SAW + ks * 16 + co) * 2);
            if (ks < 3) {
                uint32_t brow = (uint32_t)((ks + 1) * 16) + brow0;
                ldm_x4_t(b2[nxt],     uB + (brow * SBW + wn * 32 + co) * 2);
                ldm_x4_t(b2[nxt] + 4, uB + (brow * SBW + wn * 32 + 16 + co) * 2);
            }
            #pragma unroll
            for (int mt = 0; mt < 4; ++mt) {
                if (mt < 3)
                    ldm_x4(a2[(mt + 1) & 1],
                           uA + ((arow + (mt + 1) * 16) * SAW + ks * 16 + co) * 2);
                const uint32_t* am = a2[mt & 1];
                mma16816(acc[mt][0], am, b2[cur][0], b2[cur][1]);
                mma16816(acc[mt][1], am, b2[cur][2], b2[cur][3]);
                mma16816(acc[mt][2], am, b2[cur][4], b2[cur][5]);
                mma16816(acc[mt][3], am, b2[cur][6], b2[cur][7]);
            }
        }
        if (ck + 2 < NCK) dn_issue(ck + 2, (ck + 2) % 3, sbd, sPair, dw, cb, tid);
    }

    // epilogue: per-pair fp16 scratch
    #pragma unroll
    for (int mt = 0; mt < 4; ++mt)
        #pragma unroll
        for (int j = 0; j < 4; ++j) {
            int c = cb * 128 + wn * 32 + j * 8 + (lane & 3) * 2;
            #pragma unroll
            for (int half = 0; half < 2; ++half) {
                int r = wm * 64 + mt * 16 + (lane >> 2) + half * 8;
                int pr = sPair[r];
                if (pr < 0) continue;
                *(uint32_t*)(g_ds + (size_t)pr * HD + c) =
                    pkh(__float2half_rn(acc[mt][j][half * 2]),
                        __float2half_rn(acc[mt][j][half * 2 + 1]));
            }
        }
}

// ============================ combine ============================
__global__ void k_combine(float* __restrict__ out) {
    int idx = blockIdx.x * blockDim.x + threadIdx.x;
    int t  = idx >> 9;
    int c4 = idx & 511;
    const uint2* s2 = (const uint2*)g_ds;
    uint2 ua = s2[(size_t)(2 * t) * 512 + c4];
    uint2 ub = s2[(size_t)(2 * t + 1) * 512 + c4];
    __half2 a0 = *(__half2*)&ua.x, a1 = *(__half2*)&ua.y;
    __half2 b0 = *(__half2*)&ub.x, b1 = *(__half2*)&ub.y;
    float2 fa0 = __half22float2(a0), fa1 = __half22float2(a1);
    float2 fb0 = __half22float2(b0), fb1 = __half22float2(b1);
    ((float4*)out)[idx] = make_float4(fa0.x + fb0.x, fa0.y + fb0.y,
                                      fa1.x + fb1.x, fa1.y + fb1.y);
}

// ============================ host ============================
extern "C" void kernel_launch(void* const* d_in, const int* in_sizes, int n_in,
                              void* d_out, int out_size)
{
    const float* x      = (const float*)d_in[0];
    const int*   sel    = (const int*)  d_in[1];
    const float* rw     = (const float*)d_in[2];
    const float* gate_w = (const float*)d_in[3];
    const float* up_w   = (const float*)d_in[4];
    const float* down_w = (const float*)d_in[5];
    float* out = (float*)d_out;

    cudaFuncSetAttribute(k_gateup, cudaFuncAttributeMaxDynamicSharedMemorySize, SMEM_SZ);
    cudaFuncSetAttribute(k_down,   cudaFuncAttributeMaxDynamicSharedMemorySize, SMEM_SZ);

    __half *xh, *gw, *uw, *dww;
    cudaGetSymbolAddress((void**)&xh,  g_x_h);
    cudaGetSymbolAddress((void**)&gw,  g_gw);
    cudaGetSymbolAddress((void**)&uw,  g_uw);
    cudaGetSymbolAddress((void**)&dww, g_dw);
    int nx4 = NT * HD / 4;
    int nw4 = NE * HD * ID / 4;

    k_zero_counts<<<1, 32>>>();                                   // 0
    k_route<<<MAXP / 256, 256>>>(sel);                            // 1
    k_half8<<<(nx4 / 2 + 255) / 256, 256>>>(x, xh, nx4);          // 2
    k_half8<<<(nw4 / 2 + 255) / 256, 256>>>(gate_w, gw, nw4);     // 3
    k_half8<<<(nw4 / 2 + 255) / 256, 256>>>(up_w,   uw, nw4);     // 4

    dim3 g1(ID / 64, MAXP / 128, NE);                             // 5
    k_gateup<<<g1, 256, SMEM_SZ>>>(rw);

    k_half8<<<(nw4 / 2 + 255) / 256, 256>>>(down_w, dww, nw4);    // 6

    dim3 g2(HD / 128, MAXP / 128, NE);                            // 7
    k_down<<<g2, 256, SMEM_SZ>>>();

    k_combine<<<(NT * HD / 4) / 256, 256>>>(out);                 // 8
}